// round 15
// baseline (speedup 1.0000x reference)
#include <cuda_runtime.h>
#include <cuda_pipeline.h>
#include <math.h>
#include <float.h>

// Problem constants
#define BB   8
#define TT   128
#define DD   512
#define MM   256
#define TOPK 8
#define NHH  2
#define BT   (BB*TT)   // 1024

// ---------------- scratch ----------------
__device__ __align__(16) float g_kj  [BT*NHH*DD];
__device__ __align__(16) float g_vk  [BT*NHH*DD];
__device__ __align__(16) float g_vv  [BT*NHH*DD];
__device__ __align__(16) float g_beta[BT*NHH];
__device__ __align__(16) float g_kinv[BT*NHH];
__device__ __align__(16) float g_gate[BT*DD];
__device__ __align__(16) float g_RO  [BT*DD];
__device__ __align__(16) float g_attn[BT*TOPK];   // K-CTA -> V-CTA mailbox
__device__           int   g_aflag[BT];           // release flags (reset by addr_kernel)
__device__           int   g_widx[BT*TOPK];
__device__ __align__(16) float g_ww  [BT*TOPK];
__device__ __align__(16) float g_dec [BT*TOPK];
__device__           int   g_ridx[BT*TOPK];

// ---------------- init (float4 SM copy) ----------------
__global__ void init_kernel(const float* __restrict__ Ki, const float* __restrict__ Vi,
                            const float* __restrict__ zKi, const float* __restrict__ zVi,
                            float* __restrict__ oK, float* __restrict__ oV,
                            float* __restrict__ ozK, float* __restrict__ ozV)
{
    int i = blockIdx.x * blockDim.x + threadIdx.x;
    const int n = BB * MM * DD / 4;
    if (i < n) {
        ((float4*)oK)[i] = ((const float4*)Ki)[i];
        ((float4*)oV)[i] = ((const float4*)Vi)[i];
    }
    if (i < BB * MM) { ozK[i] = zKi[i]; ozV[i] = zVi[i]; }
}

// ---------------- fused addressing + decay (exact fp32) ----------------
__global__ __launch_bounds__(64) void addr_kernel(
    const float* __restrict__ h,
    const float* __restrict__ W_k, const float* __restrict__ W_q,
    const float* __restrict__ ltw, const float* __restrict__ ltr,
    const float* __restrict__ gammap)
{
    int bt   = blockIdx.x;
    int warp = threadIdx.x >> 5;
    int lane = threadIdx.x & 31;
    if (threadIdx.x == 0) g_aflag[bt] = 0;        // reset mailbox each launch/replay
    const float* W = (warp == 0) ? W_k : W_q;
    float tau = expf((warp == 0 ? ltw : ltr)[0]);
    float spg = log1pf(expf(gammap[0]));

    const float4* h4 = (const float4*)(h + (size_t)bt * DD);
    float4 hreg[4];
#pragma unroll
    for (int i = 0; i < 4; i++) hreg[i] = h4[lane + 32 * i];

    float myz = 0.f;
#pragma unroll 4
    for (int d = 0; d < 32; d++) {
        const float4* w4 = (const float4*)(W + (size_t)d * DD);
        float p = 0.f;
#pragma unroll
        for (int i = 0; i < 4; i++) {
            float4 w = w4[lane + 32 * i];
            p += hreg[i].x * w.x + hreg[i].y * w.y + hreg[i].z * w.z + hreg[i].w * w.w;
        }
#pragma unroll
        for (int o = 16; o > 0; o >>= 1) p += __shfl_xor_sync(0xffffffffu, p, o);
        if (lane == d) myz = p;
    }

    float zhi = __shfl_sync(0xffffffffu, myz, (lane + 16) & 31);
    float x0 = (lane < 16) ? myz / tau : -FLT_MAX;
    float x1 = (lane < 16) ? zhi / tau : -FLT_MAX;
    float m0 = x0, m1 = x1;
#pragma unroll
    for (int o = 16; o > 0; o >>= 1) {
        m0 = fmaxf(m0, __shfl_xor_sync(0xffffffffu, m0, o));
        m1 = fmaxf(m1, __shfl_xor_sync(0xffffffffu, m1, o));
    }
    float e0 = (lane < 16) ? expf(x0 - m0) : 0.f;
    float e1 = (lane < 16) ? expf(x1 - m1) : 0.f;
    float s0 = e0, s1 = e1;
#pragma unroll
    for (int o = 16; o > 0; o >>= 1) {
        s0 += __shfl_xor_sync(0xffffffffu, s0, o);
        s1 += __shfl_xor_sync(0xffffffffu, s1, o);
    }
    float p0 = e0 / s0, p1 = e1 / s1;

    float av[8];
#pragma unroll
    for (int q = 0; q < 8; q++) {
        int idx = lane * 8 + q;
        float pi = __shfl_sync(0xffffffffu, p0, idx >> 4);
        float pj = __shfl_sync(0xffffffffu, p1, idx & 15);
        av[q] = pi * pj;
    }
    for (int k = 0; k < 8; k++) {
        float bv = -1.f; int bi = 1 << 30;
#pragma unroll
        for (int q = 0; q < 8; q++)
            if (av[q] > bv) { bv = av[q]; bi = lane * 8 + q; }
#pragma unroll
        for (int o = 16; o > 0; o >>= 1) {
            float ov = __shfl_xor_sync(0xffffffffu, bv, o);
            int   oi = __shfl_xor_sync(0xffffffffu, bi, o);
            if (ov > bv || (ov == bv && oi < bi)) { bv = ov; bi = oi; }
        }
        if (lane == 0) {
            if (warp == 0) {
                g_widx[bt * 8 + k] = bi;
                g_ww  [bt * 8 + k] = bv;
                g_dec [bt * 8 + k] = powf(1.0f - bv, spg);
            } else {
                g_ridx[bt * 8 + k] = bi;
            }
        }
        if ((bi >> 3) == lane) av[bi & 7] = -2.f;
    }
}

// ---------------- mega GEMM (FFMA): {hh_k(silu), hh_vk, hh_vv, W_gate} ----------------
__global__ __launch_bounds__(256) void mega_gemm(
    const float* __restrict__ h,
    const float* __restrict__ hh_k, const float* __restrict__ hh_vk,
    const float* __restrict__ hh_vv, const float* __restrict__ W_gate)
{
    int nt = blockIdx.x, mt = blockIdx.y;
    const float* Bb; float* Cd; int ldc, ncol0, act = 0;
    if (nt < 8)       { Bb = hh_k   + (size_t)nt        * 128 * DD; Cd = g_kj;   ldc = NHH * DD; ncol0 = nt        * 128; act = 1; }
    else if (nt < 16) { Bb = hh_vk  + (size_t)(nt - 8)  * 128 * DD; Cd = g_vk;   ldc = NHH * DD; ncol0 = (nt - 8)  * 128; }
    else if (nt < 24) { Bb = hh_vv  + (size_t)(nt - 16) * 128 * DD; Cd = g_vv;   ldc = NHH * DD; ncol0 = (nt - 16) * 128; }
    else              { Bb = W_gate + (size_t)(nt - 24) * 128 * DD; Cd = g_gate; ldc = DD;       ncol0 = (nt - 24) * 128; }
    const float* Ab = h + (size_t)mt * 128 * DD;

    __shared__ float As[16][132];
    __shared__ float Bs[16][132];
    int tid = threadIdx.x;
    int tx = tid & 15, ty = tid >> 4;
    int lr = tid >> 2;
    int lc = (tid & 3) * 4;

    float acc[8][8];
#pragma unroll
    for (int i = 0; i < 8; i++)
#pragma unroll
        for (int j = 0; j < 8; j++) acc[i][j] = 0.f;

    float4 pa0 = *(const float4*)(Ab + (size_t)lr        * DD + lc);
    float4 pa1 = *(const float4*)(Ab + (size_t)(lr + 64) * DD + lc);
    float4 pb0 = *(const float4*)(Bb + (size_t)lr        * DD + lc);
    float4 pb1 = *(const float4*)(Bb + (size_t)(lr + 64) * DD + lc);

    for (int k0 = 0; k0 < DD; k0 += 16) {
        As[lc + 0][lr]      = pa0.x; As[lc + 1][lr]      = pa0.y; As[lc + 2][lr]      = pa0.z; As[lc + 3][lr]      = pa0.w;
        As[lc + 0][lr + 64] = pa1.x; As[lc + 1][lr + 64] = pa1.y; As[lc + 2][lr + 64] = pa1.z; As[lc + 3][lr + 64] = pa1.w;
        Bs[lc + 0][lr]      = pb0.x; Bs[lc + 1][lr]      = pb0.y; Bs[lc + 2][lr]      = pb0.z; Bs[lc + 3][lr]      = pb0.w;
        Bs[lc + 0][lr + 64] = pb1.x; Bs[lc + 1][lr + 64] = pb1.y; Bs[lc + 2][lr + 64] = pb1.z; Bs[lc + 3][lr + 64] = pb1.w;
        __syncthreads();
        if (k0 + 16 < DD) {
            int kn = k0 + 16;
            pa0 = *(const float4*)(Ab + (size_t)lr        * DD + kn + lc);
            pa1 = *(const float4*)(Ab + (size_t)(lr + 64) * DD + kn + lc);
            pb0 = *(const float4*)(Bb + (size_t)lr        * DD + kn + lc);
            pb1 = *(const float4*)(Bb + (size_t)(lr + 64) * DD + kn + lc);
        }
#pragma unroll
        for (int kk = 0; kk < 16; kk++) {
            float4 a0 = *(const float4*)&As[kk][ty * 8];
            float4 a1 = *(const float4*)&As[kk][ty * 8 + 4];
            float4 b0 = *(const float4*)&Bs[kk][tx * 8];
            float4 b1 = *(const float4*)&Bs[kk][tx * 8 + 4];
            float avv[8] = {a0.x, a0.y, a0.z, a0.w, a1.x, a1.y, a1.z, a1.w};
            float bvv[8] = {b0.x, b0.y, b0.z, b0.w, b1.x, b1.y, b1.z, b1.w};
#pragma unroll
            for (int i = 0; i < 8; i++)
#pragma unroll
                for (int j = 0; j < 8; j++)
                    acc[i][j] += avv[i] * bvv[j];
        }
        __syncthreads();
    }

#pragma unroll
    for (int i = 0; i < 8; i++) {
        int row = mt * 128 + ty * 8 + i;
        float* crow = Cd + (size_t)row * ldc + ncol0 + tx * 8;
        float v[8];
#pragma unroll
        for (int j = 0; j < 8; j++) {
            v[j] = acc[i][j];
            if (act) v[j] = v[j] / (1.0f + expf(-v[j]));
        }
        *(float4*)&crow[0] = make_float4(v[0], v[1], v[2], v[3]);
        *(float4*)&crow[4] = make_float4(v[4], v[5], v[6], v[7]);
    }
}

// ---------------- final gated GEMM (FFMA): grid (8, 16) ----------------
__global__ __launch_bounds__(256) void out_gemm(const float* __restrict__ W_out,
                                                float* __restrict__ C)
{
    int nt = blockIdx.x, mt = blockIdx.y;
    const float* Ab = g_RO + (size_t)mt * 64 * DD;
    const float* Bb = W_out + (size_t)nt * 64 * DD;

    __shared__ float As[16][68];
    __shared__ float Bs[16][68];
    int tid = threadIdx.x;
    int tx = tid & 15, ty = tid >> 4;
    int lr = tid >> 2;
    int lc = (tid & 3) * 4;

    float acc[4][4];
#pragma unroll
    for (int i = 0; i < 4; i++)
#pragma unroll
        for (int j = 0; j < 4; j++) acc[i][j] = 0.f;

    float4 pa = *(const float4*)(Ab + (size_t)lr * DD + lc);
    float4 pb = *(const float4*)(Bb + (size_t)lr * DD + lc);

    for (int k0 = 0; k0 < DD; k0 += 16) {
        As[lc + 0][lr] = pa.x; As[lc + 1][lr] = pa.y; As[lc + 2][lr] = pa.z; As[lc + 3][lr] = pa.w;
        Bs[lc + 0][lr] = pb.x; Bs[lc + 1][lr] = pb.y; Bs[lc + 2][lr] = pb.z; Bs[lc + 3][lr] = pb.w;
        __syncthreads();
        if (k0 + 16 < DD) {
            int kn = k0 + 16;
            pa = *(const float4*)(Ab + (size_t)lr * DD + kn + lc);
            pb = *(const float4*)(Bb + (size_t)lr * DD + kn + lc);
        }
#pragma unroll
        for (int kk = 0; kk < 16; kk++) {
            float4 a0 = *(const float4*)&As[kk][ty * 4];
            float4 b0 = *(const float4*)&Bs[kk][tx * 4];
            float avv[4] = {a0.x, a0.y, a0.z, a0.w};
            float bvv[4] = {b0.x, b0.y, b0.z, b0.w};
#pragma unroll
            for (int i = 0; i < 4; i++)
#pragma unroll
                for (int j = 0; j < 4; j++)
                    acc[i][j] += avv[i] * bvv[j];
        }
        __syncthreads();
    }

#pragma unroll
    for (int i = 0; i < 4; i++) {
        int row = mt * 64 + ty * 4 + i;
        int col0 = nt * 64 + tx * 4;
        const float* grow = g_gate + (size_t)row * DD + col0;
        float* crow = C + (size_t)row * DD + col0;
        float v[4];
#pragma unroll
        for (int j = 0; j < 4; j++)
            v[j] = acc[i][j] * (1.0f / (1.0f + expf(-grow[j])));
        *(float4*)crow = make_float4(v[0], v[1], v[2], v[3]);
    }
}

// ---------------- norm (1/||kj||) + beta, fused ----------------
__global__ void norm_kernel(const float* __restrict__ h, const float* __restrict__ bw,
                            const float* __restrict__ bb)
{
    int row = blockIdx.x;
    int tid = threadIdx.x;
    int bt = row >> 1, j = row & 1;
    const float* src = g_kj + (size_t)row * DD;
    const float* hp  = h   + (size_t)bt  * DD;
    const float* wp  = bw  + (size_t)j   * DD;
    float s = 0.f, bsum = 0.f;
#pragma unroll
    for (int q = 0; q < 4; q++) {
        float v = src[tid + 128 * q];
        s += v * v;
        bsum += hp[tid + 128 * q] * wp[tid + 128 * q];
    }
#pragma unroll
    for (int o = 16; o > 0; o >>= 1) {
        s    += __shfl_xor_sync(0xffffffffu, s, o);
        bsum += __shfl_xor_sync(0xffffffffu, bsum, o);
    }
    __shared__ float sh1[4], sh2[4];
    if ((tid & 31) == 0) { sh1[tid >> 5] = s; sh2[tid >> 5] = bsum; }
    __syncthreads();
    if (tid == 0) {
        float tot = sh1[0] + sh1[1] + sh1[2] + sh1[3];
        float bt2 = sh2[0] + sh2[1] + sh2[2] + sh2[3];
        g_kinv[row] = 1.0f / fmaxf(sqrtf(tot), 1e-12f);
        g_beta[row] = 2.0f / (1.0f + expf(-(bt2 + bb[j])));
    }
}

// ---------------- split sequential scan: 2 CTAs per batch (K producer / V consumer) ----------------
// grid = 16, block = 256. role = blockIdx.x & 1: 0 = K-CTA, 1 = V-CTA.
// Coupling: K publishes attn[8]/step via lane-0-only store + threadfence + volatile flag;
// V spins (volatile) then fence + __ldcg. One-way -> deadlock-free.
// dynamic smem (floats):
//   [0,2048)      kj  [2][1024]
//   [2048,4096)   vx  [2][1024]   (vk for K, vv for V)
//   [4096,5120)   h   [2][512]    (K only)
//   [5120,9216)   Vn  [8][512]    (V only)
//   [9216,13312)  Wr  [8][512]
//   [13312,17408) Wn  [8][512]
//   [17408,25600) Rn  [2][8][512]
//   [25600,25856) z   [256]
#define SEQ_SMEM_FLOATS 25856
__global__ void __launch_bounds__(256) seq_kernel(
    const float* __restrict__ h,
    float* __restrict__ Ks, float* __restrict__ Vs,
    float* __restrict__ zK, float* __restrict__ zV)
{
    extern __shared__ __align__(16) float sm[];
    float* sm_kj = sm;
    float* sm_vx = sm + 2048;
    float* sm_h  = sm + 4096;
    float* sm_Vn = sm + 5120;
    float* sm_Wr = sm + 9216;
    float* sm_Wn = sm + 13312;
    float* sm_Rn = sm + 17408;
    float* s_z   = sm + 25600;

    __shared__ int   s_widx[2][8], s_ridx[2][8];
    __shared__ float s_dec[2][8], s_ww[2][8], s_beta[2][2], s_inv[2][2];
    __shared__ float s_rel[8];

    int b    = blockIdx.x >> 1;
    bool isV = (blockIdx.x & 1) != 0;
    int tid  = threadIdx.x;
    int warp = tid >> 5, lane = tid & 31;
    int r    = warp;                    // 0..7, one state row per warp
    const float scale = 1.0f / sqrtf((float)DD);

    float4* myBase = (float4*)((isV ? Vs : Ks) + (size_t)b * MM * DD);
    float*  zG  = (isV ? zV : zK) + b * MM;
    const float* gvx = isV ? g_vv : g_vk;
    float4* myWn = (float4*)(sm_Wn + warp * DD);
    float4* myWr = (float4*)(sm_Wr + warp * DD);

    const int NSTG = isV ? 512 : 640;   // float4 count: kj 256 + vx 256 (+ h 128 for K)
    auto stage_async = [&](int t, int sb) {
        int bt = b * TT + t;
        const float4* kj4 = (const float4*)(g_kj + (size_t)bt * NHH * DD);
        const float4* vx4 = (const float4*)(gvx  + (size_t)bt * NHH * DD);
        const float4* hh4 = (const float4*)(h    + (size_t)bt * DD);
        float4* dkj = (float4*)(sm_kj + sb * 1024);
        float4* dvx = (float4*)(sm_vx + sb * 1024);
        float4* dh  = (float4*)(sm_h  + sb * 512);
        for (int f = tid; f < NSTG; f += 256) {
            if      (f < 256) __pipeline_memcpy_async(dkj + f,       kj4 + f,       16);
            else if (f < 512) __pipeline_memcpy_async(dvx + (f-256), vx4 + (f-256), 16);
            else              __pipeline_memcpy_async(dh  + (f-512), hh4 + (f-512), 16);
        }
    };
    auto stage_scalars = [&](int t, int sb) {
        int bt = b * TT + t;
        if (tid < 8) {
            s_widx[sb][tid] = g_widx[bt * TOPK + tid];
            s_ridx[sb][tid] = g_ridx[bt * TOPK + tid];
            s_dec [sb][tid] = g_dec [bt * TOPK + tid];
            s_ww  [sb][tid] = g_ww  [bt * TOPK + tid];
        } else if (tid < 10) {
            s_beta[sb][tid - 8] = g_beta[bt * NHH + tid - 8];
        } else if (tid < 12) {
            s_inv [sb][tid - 10] = g_kinv[bt * NHH + tid - 10];
        }
    };
    auto prefetch_rows_async = [&](int sb) {
        int ws = s_widx[sb][r];
        int rs = s_ridx[sb][r];
        const float4* wb = myBase + ws * (DD / 4);
        const float4* rb = myBase + rs * (DD / 4);
        float4* dR = (float4*)(sm_Rn + sb * 4096 + warp * DD);
#pragma unroll
        for (int i = 0; i < 4; i++) {
            __pipeline_memcpy_async(&myWn[lane + 32 * i], &wb[lane + 32 * i], 16);
            __pipeline_memcpy_async(&dR  [lane + 32 * i], &rb[lane + 32 * i], 16);
        }
    };

    // ---------------- prologue: synchronous staging of step 0 ----------------
    for (int i = tid; i < MM; i += 256) s_z[i] = zG[i];
    {
        int bt0 = b * TT;
        const float4* kj4 = (const float4*)(g_kj + (size_t)bt0 * NHH * DD);
        const float4* vx4 = (const float4*)(gvx  + (size_t)bt0 * NHH * DD);
        const float4* hh4 = (const float4*)(h    + (size_t)bt0 * DD);
        for (int f = tid; f < NSTG; f += 256) {
            if      (f < 256) ((float4*)sm_kj)[f]       = kj4[f];
            else if (f < 512) ((float4*)sm_vx)[f - 256] = vx4[f - 256];
            else              ((float4*)sm_h )[f - 512] = hh4[f - 512];
        }
    }
    stage_scalars(0, 0);
    __syncthreads();
    {   // synchronous row fetch for t=0
        int ws = s_widx[0][r], rs = s_ridx[0][r];
        const float4* wb = myBase + ws * (DD / 4);
        const float4* rb = myBase + rs * (DD / 4);
        float4* dR = (float4*)(sm_Rn + warp * DD);
#pragma unroll
        for (int i = 0; i < 4; i++) {
            myWn[lane + 32 * i] = wb[lane + 32 * i];
            dR  [lane + 32 * i] = rb[lane + 32 * i];
        }
    }
    __syncthreads();

    for (int t = 0; t < TT; t++) {
        int bt = b * TT + t;
        int pb = t & 1, nb = pb ^ 1;

        if (t + 1 < TT) {
            stage_async(t + 1, nb);
            __pipeline_commit();
            stage_scalars(t + 1, nb);
        }

        // ---- write phase: delta-rule on own state's 8 written rows ----
        {
            float decay = s_dec[pb][r];
            float4 row[4];
#pragma unroll
            for (int i = 0; i < 4; i++) {
                float4 v = myWn[lane + 32 * i];
                row[i] = make_float4(v.x * decay, v.y * decay, v.z * decay, v.w * decay);
            }
            if (warp == 0 && lane < 8) {     // own z update
                int sl = s_widx[pb][lane];
                float wl = s_ww[pb][lane];
                float dl = s_dec[pb][lane];
                s_z[sl] = dl * s_z[sl] + wl;
            }
#pragma unroll
            for (int j = 0; j < NHH; j++) {
                float be   = s_beta[pb][j];
                float invj = s_inv [pb][j];
                const float4* KJ = (const float4*)(sm_kj + pb * 1024 + j * DD);
                const float4* VX = (const float4*)(sm_vx + pb * 1024 + j * DD);
                float4 kj4[4];
                float p = 0.f;
#pragma unroll
                for (int i = 0; i < 4; i++) {
                    kj4[i] = KJ[lane + 32 * i];
                    p += kj4[i].x * row[i].x + kj4[i].y * row[i].y
                       + kj4[i].z * row[i].z + kj4[i].w * row[i].w;
                }
#pragma unroll
                for (int o = 16; o > 0; o >>= 1) p += __shfl_xor_sync(0xffffffffu, p, o);
                float cb = be * invj * invj * p;
#pragma unroll
                for (int i = 0; i < 4; i++) {
                    float4 vx4 = VX[lane + 32 * i];
                    row[i].x += be * kj4[i].x * vx4.x - cb * kj4[i].x;
                    row[i].y += be * kj4[i].y * vx4.y - cb * kj4[i].y;
                    row[i].z += be * kj4[i].z * vx4.z - cb * kj4[i].z;
                    row[i].w += be * kj4[i].w * vx4.w - cb * kj4[i].w;
                }
            }
            float4* gbase = myBase + s_widx[pb][r] * (DD / 4);
#pragma unroll
            for (int i = 0; i < 4; i++) {
                gbase[lane + 32 * i] = row[i];
                myWr [lane + 32 * i] = row[i];
            }
        }
        __syncthreads();   // A: state STG + Wr + z + scalars(t+1) visible; Wn free

        if (t + 1 < TT) {
            prefetch_rows_async(nb);
            __pipeline_commit();
        }

        // ---- read phase ----
        {
            int rslot = s_ridx[pb][r];
            int rm = -1;
#pragma unroll
            for (int q = 0; q < 8; q++) if (s_widx[pb][q] == rslot) rm = q;
            const float4* rsrc = (rm >= 0)
                ? (const float4*)(sm_Wr + rm * DD)
                : (const float4*)(sm_Rn + pb * 4096 + warp * DD);
            if (!isV) {
                const float4* H4 = (const float4*)(sm_h + pb * 512);
                float p = 0.f;
#pragma unroll
                for (int i = 0; i < 4; i++) {
                    float4 k4 = rsrc[lane + 32 * i];
                    float4 h4 = H4[lane + 32 * i];
                    p += k4.x * h4.x + k4.y * h4.y + k4.z * h4.z + k4.w * h4.w;
                }
#pragma unroll
                for (int o = 16; o > 0; o >>= 1) p += __shfl_xor_sync(0xffffffffu, p, o);
                if (lane == 0) s_rel[r] = p / s_z[rslot];
            } else {
                float invz = 1.0f / s_z[rslot];
                float4* dst = (float4*)(sm_Vn + r * DD);
#pragma unroll
                for (int i = 0; i < 4; i++) {
                    float4 v = rsrc[lane + 32 * i];
                    dst[lane + 32 * i] = make_float4(v.x * invz, v.y * invz,
                                                     v.z * invz, v.w * invz);
                }
            }
        }

        if (t + 1 < TT) __pipeline_wait_prior(0);
        __syncthreads();   // B: s_rel/Vn + staged buffers + prefetched rows visible

        if (!isV) {
            // ---- K-CTA: softmax (warp 0, full-warp collectives) -> lane-0 publish ----
            if (warp == 0) {
                float x = s_rel[lane & 7] * scale;
                float m = x;
#pragma unroll
                for (int o = 4; o > 0; o >>= 1) m = fmaxf(m, __shfl_xor_sync(0xffffffffu, m, o));
                float e = expf(x - m);
                float ssum = e;
#pragma unroll
                for (int o = 4; o > 0; o >>= 1) ssum += __shfl_xor_sync(0xffffffffu, ssum, o);
                float a = e / ssum;
                float av[8];
#pragma unroll
                for (int q = 0; q < 8; q++) av[q] = __shfl_sync(0xffffffffu, a, q);  // ALL lanes execute
                if (lane == 0) {
                    float* dst = g_attn + (size_t)bt * TOPK;
#pragma unroll
                    for (int q = 0; q < 8; q++) dst[q] = av[q];
                    __threadfence();
                    ((volatile int*)g_aflag)[bt] = 1;
                }
            }
        } else {
            // ---- V-CTA: acquire attn, readout (2 elems/thread) ----
            volatile int* vf = (volatile int*)(g_aflag + bt);
            while (*vf == 0) { }
            __threadfence();
            const float* asrc = g_attn + (size_t)bt * TOPK;
            float attn[8];
#pragma unroll
            for (int q = 0; q < 8; q++) attn[q] = __ldcg(asrc + q);
            float acc0 = 0.f, acc1 = 0.f;
#pragma unroll
            for (int i = 0; i < 8; i++) {
                acc0 += attn[i] * sm_Vn[i * DD + tid];
                acc1 += attn[i] * sm_Vn[i * DD + tid + 256];
            }
            g_RO[(size_t)bt * DD + tid]       = acc0;
            g_RO[(size_t)bt * DD + tid + 256] = acc1;
        }
        // no barrier here: Vn/s_rel writers for t+1 are behind A(t+1)/B(t+1)
    }

    for (int i = tid; i < MM; i += 256) zG[i] = s_z[i];
}

// ---------------- final index outputs ----------------
__global__ void idxout_kernel(float* __restrict__ ow, float* __restrict__ orr)
{
    int k = threadIdx.x;
    if (k < BB * TOPK) {
        int b = k >> 3, q = k & 7;
        ow [k] = (float)g_widx[(b * TT + TT - 1) * TOPK + q];
        orr[k] = (float)g_ridx[(b * TT + TT - 1) * TOPK + q];
    }
}

// ---------------- launch ----------------
extern "C" void kernel_launch(void* const* d_in, const int* in_sizes, int n_in,
                              void* d_out, int out_size)
{
    const float* h      = (const float*)d_in[0];
    const float* Kslots = (const float*)d_in[1];
    const float* Vslots = (const float*)d_in[2];
    const float* zKin   = (const float*)d_in[3];
    const float* zVin   = (const float*)d_in[4];
    const float* W_k    = (const float*)d_in[5];
    const float* W_q    = (const float*)d_in[6];
    const float* ltw    = (const float*)d_in[7];
    const float* ltr    = (const float*)d_in[8];
    const float* hh_k   = (const float*)d_in[9];
    const float* hh_vk  = (const float*)d_in[10];
    const float* hh_vv  = (const float*)d_in[11];
    const float* hh_bw  = (const float*)d_in[12];
    const float* hh_bb  = (const float*)d_in[13];
    const float* gamma  = (const float*)d_in[14];
    const float* W_out  = (const float*)d_in[15];
    const float* W_gate = (const float*)d_in[16];

    float* out    = (float*)d_out;
    float* o_outs = out;
    float* o_K    = o_outs + (size_t)BB * TT * DD;
    float* o_V    = o_K    + (size_t)BB * MM * DD;
    float* o_zK   = o_V    + (size_t)BB * MM * DD;
    float* o_zV   = o_zK   + BB * MM;
    float* o_wi   = o_zV   + BB * MM;
    float* o_ri   = o_wi   + BB * TOPK;

    cudaFuncSetAttribute(seq_kernel, cudaFuncAttributeMaxDynamicSharedMemorySize,
                         SEQ_SMEM_FLOATS * (int)sizeof(float));

    init_kernel<<<(BB * MM * DD / 4 + 255) / 256, 256>>>(Kslots, Vslots, zKin, zVin,
                                                         o_K, o_V, o_zK, o_zV);
    addr_kernel<<<BT, 64>>>(h, W_k, W_q, ltw, ltr, gamma);
    mega_gemm<<<dim3(28, 8), 256>>>(h, hh_k, hh_vk, hh_vv, W_gate);
    norm_kernel<<<BT * NHH, 128>>>(h, hh_bw, hh_bb);

    seq_kernel<<<2 * BB, 256, SEQ_SMEM_FLOATS * sizeof(float)>>>(h, o_K, o_V, o_zK, o_zV);

    out_gemm<<<dim3(8, 16), 256>>>(W_out, o_outs);
    idxout_kernel<<<1, 64>>>(o_wi, o_ri);
}

// round 16
// speedup vs baseline: 1.1881x; 1.1881x over previous
#include <cuda_runtime.h>
#include <cuda_pipeline.h>
#include <math.h>
#include <float.h>

// Problem constants
#define BB   8
#define TT   128
#define DD   512
#define MM   256
#define TOPK 8
#define NHH  2
#define BT   (BB*TT)   // 1024

// ---------------- scratch ----------------
__device__ __align__(16) float g_kj  [BT*NHH*DD];
__device__ __align__(16) float g_vk  [BT*NHH*DD];
__device__ __align__(16) float g_vv  [BT*NHH*DD];
__device__ __align__(16) float g_beta[BT*NHH];
__device__ __align__(16) float g_kinv[BT*NHH];
__device__ __align__(16) float g_gate[BT*DD];
__device__ __align__(16) float g_RO  [BT*DD];
__device__           int   g_widx[BT*TOPK];
__device__ __align__(16) float g_ww  [BT*TOPK];
__device__ __align__(16) float g_dec [BT*TOPK];
__device__           int   g_ridx[BT*TOPK];
__device__           int   g_rmatch[BT*TOPK];   // reader->writer collision (-1 = none)

// ---------------- init (float4 SM copy) ----------------
__global__ void init_kernel(const float* __restrict__ Ki, const float* __restrict__ Vi,
                            const float* __restrict__ zKi, const float* __restrict__ zVi,
                            float* __restrict__ oK, float* __restrict__ oV,
                            float* __restrict__ ozK, float* __restrict__ ozV)
{
    int i = blockIdx.x * blockDim.x + threadIdx.x;
    const int n = BB * MM * DD / 4;
    if (i < n) {
        ((float4*)oK)[i] = ((const float4*)Ki)[i];
        ((float4*)oV)[i] = ((const float4*)Vi)[i];
    }
    if (i < BB * MM) { ozK[i] = zKi[i]; ozV[i] = zVi[i]; }
}

// ---------------- fused addressing + decay + rmatch + final-index outputs ----------------
__global__ __launch_bounds__(64) void addr_kernel(
    const float* __restrict__ h,
    const float* __restrict__ W_k, const float* __restrict__ W_q,
    const float* __restrict__ ltw, const float* __restrict__ ltr,
    const float* __restrict__ gammap,
    float* __restrict__ ow, float* __restrict__ orr)
{
    int bt   = blockIdx.x;
    int warp = threadIdx.x >> 5;
    int lane = threadIdx.x & 31;
    const float* W = (warp == 0) ? W_k : W_q;
    float tau = expf((warp == 0 ? ltw : ltr)[0]);
    float spg = log1pf(expf(gammap[0]));

    __shared__ int sh_w[8], sh_r[8];

    const float4* h4 = (const float4*)(h + (size_t)bt * DD);
    float4 hreg[4];
#pragma unroll
    for (int i = 0; i < 4; i++) hreg[i] = h4[lane + 32 * i];

    float myz = 0.f;
#pragma unroll 4
    for (int d = 0; d < 32; d++) {
        const float4* w4 = (const float4*)(W + (size_t)d * DD);
        float p = 0.f;
#pragma unroll
        for (int i = 0; i < 4; i++) {
            float4 w = w4[lane + 32 * i];
            p += hreg[i].x * w.x + hreg[i].y * w.y + hreg[i].z * w.z + hreg[i].w * w.w;
        }
#pragma unroll
        for (int o = 16; o > 0; o >>= 1) p += __shfl_xor_sync(0xffffffffu, p, o);
        if (lane == d) myz = p;
    }

    float zhi = __shfl_sync(0xffffffffu, myz, (lane + 16) & 31);
    float x0 = (lane < 16) ? myz / tau : -FLT_MAX;
    float x1 = (lane < 16) ? zhi / tau : -FLT_MAX;
    float m0 = x0, m1 = x1;
#pragma unroll
    for (int o = 16; o > 0; o >>= 1) {
        m0 = fmaxf(m0, __shfl_xor_sync(0xffffffffu, m0, o));
        m1 = fmaxf(m1, __shfl_xor_sync(0xffffffffu, m1, o));
    }
    float e0 = (lane < 16) ? expf(x0 - m0) : 0.f;
    float e1 = (lane < 16) ? expf(x1 - m1) : 0.f;
    float s0 = e0, s1 = e1;
#pragma unroll
    for (int o = 16; o > 0; o >>= 1) {
        s0 += __shfl_xor_sync(0xffffffffu, s0, o);
        s1 += __shfl_xor_sync(0xffffffffu, s1, o);
    }
    float p0 = e0 / s0, p1 = e1 / s1;

    float av[8];
#pragma unroll
    for (int q = 0; q < 8; q++) {
        int idx = lane * 8 + q;
        float pi = __shfl_sync(0xffffffffu, p0, idx >> 4);
        float pj = __shfl_sync(0xffffffffu, p1, idx & 15);
        av[q] = pi * pj;
    }
    for (int k = 0; k < 8; k++) {
        float bv = -1.f; int bi = 1 << 30;
#pragma unroll
        for (int q = 0; q < 8; q++)
            if (av[q] > bv) { bv = av[q]; bi = lane * 8 + q; }
#pragma unroll
        for (int o = 16; o > 0; o >>= 1) {
            float ov = __shfl_xor_sync(0xffffffffu, bv, o);
            int   oi = __shfl_xor_sync(0xffffffffu, bi, o);
            if (ov > bv || (ov == bv && oi < bi)) { bv = ov; bi = oi; }
        }
        if (lane == 0) {
            if (warp == 0) {
                g_widx[bt * 8 + k] = bi;
                g_ww  [bt * 8 + k] = bv;
                g_dec [bt * 8 + k] = powf(1.0f - bv, spg);
                sh_w[k] = bi;
            } else {
                g_ridx[bt * 8 + k] = bi;
                sh_r[k] = bi;
            }
        }
        if ((bi >> 3) == lane) av[bi & 7] = -2.f;
    }

    __syncthreads();
    if (threadIdx.x < 8) {
        int rs = sh_r[threadIdx.x];
        int rm = -1;
#pragma unroll
        for (int q = 0; q < 8; q++) if (sh_w[q] == rs) rm = q;
        g_rmatch[bt * 8 + threadIdx.x] = rm;
        if ((bt % TT) == TT - 1) {                  // final-step index outputs
            int bb = bt / TT;
            ow [bb * 8 + threadIdx.x] = (float)sh_w[threadIdx.x];
            orr[bb * 8 + threadIdx.x] = (float)rs;
        }
    }
}

// ---------------- mega GEMM (FFMA): {hh_k(silu), hh_vk, hh_vv, W_gate} ----------------
__global__ __launch_bounds__(256) void mega_gemm(
    const float* __restrict__ h,
    const float* __restrict__ hh_k, const float* __restrict__ hh_vk,
    const float* __restrict__ hh_vv, const float* __restrict__ W_gate)
{
    int nt = blockIdx.x, mt = blockIdx.y;
    const float* Bb; float* Cd; int ldc, ncol0, act = 0;
    if (nt < 8)       { Bb = hh_k   + (size_t)nt        * 128 * DD; Cd = g_kj;   ldc = NHH * DD; ncol0 = nt        * 128; act = 1; }
    else if (nt < 16) { Bb = hh_vk  + (size_t)(nt - 8)  * 128 * DD; Cd = g_vk;   ldc = NHH * DD; ncol0 = (nt - 8)  * 128; }
    else if (nt < 24) { Bb = hh_vv  + (size_t)(nt - 16) * 128 * DD; Cd = g_vv;   ldc = NHH * DD; ncol0 = (nt - 16) * 128; }
    else              { Bb = W_gate + (size_t)(nt - 24) * 128 * DD; Cd = g_gate; ldc = DD;       ncol0 = (nt - 24) * 128; }
    const float* Ab = h + (size_t)mt * 128 * DD;

    __shared__ float As[16][132];
    __shared__ float Bs[16][132];
    int tid = threadIdx.x;
    int tx = tid & 15, ty = tid >> 4;
    int lr = tid >> 2;
    int lc = (tid & 3) * 4;

    float acc[8][8];
#pragma unroll
    for (int i = 0; i < 8; i++)
#pragma unroll
        for (int j = 0; j < 8; j++) acc[i][j] = 0.f;

    float4 pa0 = *(const float4*)(Ab + (size_t)lr        * DD + lc);
    float4 pa1 = *(const float4*)(Ab + (size_t)(lr + 64) * DD + lc);
    float4 pb0 = *(const float4*)(Bb + (size_t)lr        * DD + lc);
    float4 pb1 = *(const float4*)(Bb + (size_t)(lr + 64) * DD + lc);

    for (int k0 = 0; k0 < DD; k0 += 16) {
        As[lc + 0][lr]      = pa0.x; As[lc + 1][lr]      = pa0.y; As[lc + 2][lr]      = pa0.z; As[lc + 3][lr]      = pa0.w;
        As[lc + 0][lr + 64] = pa1.x; As[lc + 1][lr + 64] = pa1.y; As[lc + 2][lr + 64] = pa1.z; As[lc + 3][lr + 64] = pa1.w;
        Bs[lc + 0][lr]      = pb0.x; Bs[lc + 1][lr]      = pb0.y; Bs[lc + 2][lr]      = pb0.z; Bs[lc + 3][lr]      = pb0.w;
        Bs[lc + 0][lr + 64] = pb1.x; Bs[lc + 1][lr + 64] = pb1.y; Bs[lc + 2][lr + 64] = pb1.z; Bs[lc + 3][lr + 64] = pb1.w;
        __syncthreads();
        if (k0 + 16 < DD) {
            int kn = k0 + 16;
            pa0 = *(const float4*)(Ab + (size_t)lr        * DD + kn + lc);
            pa1 = *(const float4*)(Ab + (size_t)(lr + 64) * DD + kn + lc);
            pb0 = *(const float4*)(Bb + (size_t)lr        * DD + kn + lc);
            pb1 = *(const float4*)(Bb + (size_t)(lr + 64) * DD + kn + lc);
        }
#pragma unroll
        for (int kk = 0; kk < 16; kk++) {
            float4 a0 = *(const float4*)&As[kk][ty * 8];
            float4 a1 = *(const float4*)&As[kk][ty * 8 + 4];
            float4 b0 = *(const float4*)&Bs[kk][tx * 8];
            float4 b1 = *(const float4*)&Bs[kk][tx * 8 + 4];
            float avv[8] = {a0.x, a0.y, a0.z, a0.w, a1.x, a1.y, a1.z, a1.w};
            float bvv[8] = {b0.x, b0.y, b0.z, b0.w, b1.x, b1.y, b1.z, b1.w};
#pragma unroll
            for (int i = 0; i < 8; i++)
#pragma unroll
                for (int j = 0; j < 8; j++)
                    acc[i][j] += avv[i] * bvv[j];
        }
        __syncthreads();
    }

#pragma unroll
    for (int i = 0; i < 8; i++) {
        int row = mt * 128 + ty * 8 + i;
        float* crow = Cd + (size_t)row * ldc + ncol0 + tx * 8;
        float v[8];
#pragma unroll
        for (int j = 0; j < 8; j++) {
            v[j] = acc[i][j];
            if (act) v[j] = v[j] / (1.0f + expf(-v[j]));
        }
        *(float4*)&crow[0] = make_float4(v[0], v[1], v[2], v[3]);
        *(float4*)&crow[4] = make_float4(v[4], v[5], v[6], v[7]);
    }
}

// ---------------- final gated GEMM (FFMA): grid (8, 16) ----------------
__global__ __launch_bounds__(256) void out_gemm(const float* __restrict__ W_out,
                                                float* __restrict__ C)
{
    int nt = blockIdx.x, mt = blockIdx.y;
    const float* Ab = g_RO + (size_t)mt * 64 * DD;
    const float* Bb = W_out + (size_t)nt * 64 * DD;

    __shared__ float As[16][68];
    __shared__ float Bs[16][68];
    int tid = threadIdx.x;
    int tx = tid & 15, ty = tid >> 4;
    int lr = tid >> 2;
    int lc = (tid & 3) * 4;

    float acc[4][4];
#pragma unroll
    for (int i = 0; i < 4; i++)
#pragma unroll
        for (int j = 0; j < 4; j++) acc[i][j] = 0.f;

    float4 pa = *(const float4*)(Ab + (size_t)lr * DD + lc);
    float4 pb = *(const float4*)(Bb + (size_t)lr * DD + lc);

    for (int k0 = 0; k0 < DD; k0 += 16) {
        As[lc + 0][lr] = pa.x; As[lc + 1][lr] = pa.y; As[lc + 2][lr] = pa.z; As[lc + 3][lr] = pa.w;
        Bs[lc + 0][lr] = pb.x; Bs[lc + 1][lr] = pb.y; Bs[lc + 2][lr] = pb.z; Bs[lc + 3][lr] = pb.w;
        __syncthreads();
        if (k0 + 16 < DD) {
            int kn = k0 + 16;
            pa = *(const float4*)(Ab + (size_t)lr * DD + kn + lc);
            pb = *(const float4*)(Bb + (size_t)lr * DD + kn + lc);
        }
#pragma unroll
        for (int kk = 0; kk < 16; kk++) {
            float4 a0 = *(const float4*)&As[kk][ty * 4];
            float4 b0 = *(const float4*)&Bs[kk][tx * 4];
            float avv[4] = {a0.x, a0.y, a0.z, a0.w};
            float bvv[4] = {b0.x, b0.y, b0.z, b0.w};
#pragma unroll
            for (int i = 0; i < 4; i++)
#pragma unroll
                for (int j = 0; j < 4; j++)
                    acc[i][j] += avv[i] * bvv[j];
        }
        __syncthreads();
    }

#pragma unroll
    for (int i = 0; i < 4; i++) {
        int row = mt * 64 + ty * 4 + i;
        int col0 = nt * 64 + tx * 4;
        const float* grow = g_gate + (size_t)row * DD + col0;
        float* crow = C + (size_t)row * DD + col0;
        float v[4];
#pragma unroll
        for (int j = 0; j < 4; j++)
            v[j] = acc[i][j] * (1.0f / (1.0f + expf(-grow[j])));
        *(float4*)crow = make_float4(v[0], v[1], v[2], v[3]);
    }
}

// ---------------- norm (1/||kj||) + beta, fused ----------------
__global__ void norm_kernel(const float* __restrict__ h, const float* __restrict__ bw,
                            const float* __restrict__ bb)
{
    int row = blockIdx.x;
    int tid = threadIdx.x;
    int bt = row >> 1, j = row & 1;
    const float* src = g_kj + (size_t)row * DD;
    const float* hp  = h   + (size_t)bt  * DD;
    const float* wp  = bw  + (size_t)j   * DD;
    float s = 0.f, bsum = 0.f;
#pragma unroll
    for (int q = 0; q < 4; q++) {
        float v = src[tid + 128 * q];
        s += v * v;
        bsum += hp[tid + 128 * q] * wp[tid + 128 * q];
    }
#pragma unroll
    for (int o = 16; o > 0; o >>= 1) {
        s    += __shfl_xor_sync(0xffffffffu, s, o);
        bsum += __shfl_xor_sync(0xffffffffu, bsum, o);
    }
    __shared__ float sh1[4], sh2[4];
    if ((tid & 31) == 0) { sh1[tid >> 5] = s; sh2[tid >> 5] = bsum; }
    __syncthreads();
    if (tid == 0) {
        float tot = sh1[0] + sh1[1] + sh1[2] + sh1[3];
        float bt2 = sh2[0] + sh2[1] + sh2[2] + sh2[3];
        g_kinv[row] = 1.0f / fmaxf(sqrtf(tot), 1e-12f);
        g_beta[row] = 2.0f / (1.0f + expf(-(bt2 + bb[j])));
    }
}

// ---------------- sequential scan: cp.async-pipelined, 2 barriers/step, instruction diet ----------------
// dynamic smem layout (floats):
//   [0,2048)       kj   [2][1024]
//   [2048,4096)    vk   [2][1024]
//   [4096,6144)    vv   [2][1024]
//   [6144,7168)    h    [2][512]
//   [7168,11264)   Vn   [8][512]
//   [11264,19456)  Wr   [16][512]
//   [19456,27648)  Wn   [16][512]
//   [27648,44032)  Rn   [2][16][512]
//   [44032,44288)  zK   [256]
//   [44288,44544)  zV   [256]
#define SEQ_SMEM_FLOATS 44544
__global__ void __launch_bounds__(512) seq_kernel(
    const float* __restrict__ h,
    float* __restrict__ Ks, float* __restrict__ Vs,
    float* __restrict__ zK, float* __restrict__ zV)
{
    extern __shared__ __align__(16) float sm[];
    float* sm_kj = sm;
    float* sm_vk = sm + 2048;
    float* sm_vv = sm + 4096;
    float* sm_h  = sm + 6144;
    float* sm_Vn = sm + 7168;
    float* sm_Wr = sm + 11264;
    float* sm_Wn = sm + 19456;
    float* sm_Rn = sm + 27648;
    float* s_zK  = sm + 44032;
    float* s_zV  = sm + 44288;

    __shared__ int   s_widx[2][8], s_ridx[2][8], s_rm[2][8];
    __shared__ float s_dec[2][8], s_ww[2][8], s_beta[2][2], s_inv[2][2];
    __shared__ float s_rel[8];

    int b    = blockIdx.x;
    int tid  = threadIdx.x;
    int warp = tid >> 5, lane = tid & 31;
    int r    = warp & 7;
    bool isV = warp >= 8;
    const float scale = 1.0f / sqrtf((float)DD);

    float4* KsB = (float4*)(Ks + (size_t)b * MM * DD);
    float4* VsB = (float4*)(Vs + (size_t)b * MM * DD);
    float4* myBase = isV ? VsB : KsB;
    float*  zKb = zK + b * MM;
    float*  zVb = zV + b * MM;
    float4* myWn = (float4*)(sm_Wn + warp * DD);
    float4* myWr = (float4*)(sm_Wr + warp * DD);

    // straight-line staging: thread handles 2 fixed float4 copies (896 total / 512 thr)
    auto stage_async = [&](int t, int sb) {
        int bt = b * TT + t;
        if (tid < 256) {
            const float4* kj4 = (const float4*)(g_kj + (size_t)bt * NHH * DD);
            const float4* vv4 = (const float4*)(g_vv + (size_t)bt * NHH * DD);
            __pipeline_memcpy_async((float4*)(sm_kj + sb * 1024) + tid, kj4 + tid, 16);
            __pipeline_memcpy_async((float4*)(sm_vv + sb * 1024) + tid, vv4 + tid, 16);
        } else {
            int u = tid - 256;
            const float4* vk4 = (const float4*)(g_vk + (size_t)bt * NHH * DD);
            __pipeline_memcpy_async((float4*)(sm_vk + sb * 1024) + u, vk4 + u, 16);
            if (u < 128) {
                const float4* hh4 = (const float4*)(h + (size_t)bt * DD);
                __pipeline_memcpy_async((float4*)(sm_h + sb * 512) + u, hh4 + u, 16);
            }
        }
    };
    auto stage_scalars = [&](int t, int sb) {
        int bt = b * TT + t;
        if (tid < 8) {
            s_widx[sb][tid] = g_widx[bt * TOPK + tid];
            s_ridx[sb][tid] = g_ridx[bt * TOPK + tid];
            s_dec [sb][tid] = g_dec [bt * TOPK + tid];
            s_ww  [sb][tid] = g_ww  [bt * TOPK + tid];
            s_rm  [sb][tid] = g_rmatch[bt * TOPK + tid];
        } else if (tid < 10) {
            s_beta[sb][tid - 8] = g_beta[bt * NHH + tid - 8];
        } else if (tid < 12) {
            s_inv [sb][tid - 10] = g_kinv[bt * NHH + tid - 10];
        }
    };
    auto prefetch_rows_async = [&](int sb) {
        int ws = s_widx[sb][r];
        int rs = s_ridx[sb][r];
        const float4* wb = myBase + ws * (DD / 4);
        const float4* rb = myBase + rs * (DD / 4);
        float4* dR = (float4*)(sm_Rn + sb * 8192 + warp * DD);
#pragma unroll
        for (int i = 0; i < 4; i++) {
            __pipeline_memcpy_async(&myWn[lane + 32 * i], &wb[lane + 32 * i], 16);
            __pipeline_memcpy_async(&dR  [lane + 32 * i], &rb[lane + 32 * i], 16);
        }
    };

    // prologue: synchronous staging of step 0
    for (int i = tid; i < MM; i += 512) { s_zK[i] = zKb[i]; s_zV[i] = zVb[i]; }
    {
        int bt0 = b * TT;
        const float4* kj4 = (const float4*)(g_kj + (size_t)bt0 * NHH * DD);
        const float4* vk4 = (const float4*)(g_vk + (size_t)bt0 * NHH * DD);
        const float4* vv4 = (const float4*)(g_vv + (size_t)bt0 * NHH * DD);
        const float4* hh4 = (const float4*)(h    + (size_t)bt0 * DD);
#pragma unroll 2
        for (int f = tid; f < 896; f += 512) {
            if      (f < 256) ((float4*)sm_kj)[f]       = kj4[f];
            else if (f < 512) ((float4*)sm_vk)[f - 256] = vk4[f - 256];
            else if (f < 768) ((float4*)sm_vv)[f - 512] = vv4[f - 512];
            else              ((float4*)sm_h )[f - 768] = hh4[f - 768];
        }
    }
    stage_scalars(0, 0);
    __syncthreads();
    {   // synchronous row fetch for t=0
        int ws = s_widx[0][r], rs = s_ridx[0][r];
        const float4* wb = myBase + ws * (DD / 4);
        const float4* rb = myBase + rs * (DD / 4);
        float4* dR = (float4*)(sm_Rn + warp * DD);
#pragma unroll
        for (int i = 0; i < 4; i++) {
            myWn[lane + 32 * i] = wb[lane + 32 * i];
            dR  [lane + 32 * i] = rb[lane + 32 * i];
        }
    }
    __syncthreads();

    for (int t = 0; t < TT; t++) {
        int bt = b * TT + t;
        int pb = t & 1, nb = pb ^ 1;

        if (t + 1 < TT) {
            stage_async(t + 1, nb);
            __pipeline_commit();
            stage_scalars(t + 1, nb);
        }

        // ---- write phase ----
        {
            float decay = s_dec[pb][r];
            float4 row[4];
#pragma unroll
            for (int i = 0; i < 4; i++) {
                float4 v = myWn[lane + 32 * i];
                row[i] = make_float4(v.x * decay, v.y * decay, v.z * decay, v.w * decay);
            }
            if (warp == 0) {                 // warp-uniform branch (real BRA for other warps)
                if (lane < 8) {
                    int sl = s_widx[pb][lane];
                    float wl = s_ww[pb][lane];
                    float dl = s_dec[pb][lane];
                    s_zK[sl] = dl * s_zK[sl] + wl;
                    s_zV[sl] = dl * s_zV[sl] + wl;
                }
            }
#pragma unroll
            for (int j = 0; j < NHH; j++) {
                float be   = s_beta[pb][j];
                float invj = s_inv [pb][j];
                const float4* KJ = (const float4*)(sm_kj + pb * 1024 + j * DD);
                const float4* VX = (const float4*)((isV ? sm_vv : sm_vk) + pb * 1024 + j * DD);
                float4 kj4[4];
                float p = 0.f;
#pragma unroll
                for (int i = 0; i < 4; i++) {
                    kj4[i] = KJ[lane + 32 * i];
                    p += kj4[i].x * row[i].x + kj4[i].y * row[i].y
                       + kj4[i].z * row[i].z + kj4[i].w * row[i].w;
                }
#pragma unroll
                for (int o = 16; o > 0; o >>= 1) p += __shfl_xor_sync(0xffffffffu, p, o);
                float cb = be * invj * invj * p;
#pragma unroll
                for (int i = 0; i < 4; i++) {
                    float4 vx4 = VX[lane + 32 * i];
                    row[i].x += be * kj4[i].x * vx4.x - cb * kj4[i].x;
                    row[i].y += be * kj4[i].y * vx4.y - cb * kj4[i].y;
                    row[i].z += be * kj4[i].z * vx4.z - cb * kj4[i].z;
                    row[i].w += be * kj4[i].w * vx4.w - cb * kj4[i].w;
                }
            }
            float4* gbase = myBase + s_widx[pb][r] * (DD / 4);
#pragma unroll
            for (int i = 0; i < 4; i++) {
                gbase[lane + 32 * i] = row[i];
                myWr [lane + 32 * i] = row[i];
            }
        }
        __syncthreads();   // A: state STG + Wr + z + scalars(t+1) visible; Wn free

        if (t + 1 < TT) {
            prefetch_rows_async(nb);
            __pipeline_commit();
        }

        // ---- read phase (rmatch precomputed) ----
        {
            int rslot = s_ridx[pb][r];
            int rm    = s_rm  [pb][r];
            const float4* rsrc = (rm >= 0)
                ? (const float4*)(sm_Wr + ((isV ? 8 : 0) + rm) * DD)
                : (const float4*)(sm_Rn + pb * 8192 + warp * DD);
            if (!isV) {
                const float4* H4 = (const float4*)(sm_h + pb * 512);
                float p = 0.f;
#pragma unroll
                for (int i = 0; i < 4; i++) {
                    float4 k4 = rsrc[lane + 32 * i];
                    float4 h4 = H4[lane + 32 * i];
                    p += k4.x * h4.x + k4.y * h4.y + k4.z * h4.z + k4.w * h4.w;
                }
#pragma unroll
                for (int o = 16; o > 0; o >>= 1) p += __shfl_xor_sync(0xffffffffu, p, o);
                if (lane == 0) s_rel[r] = p / s_zK[rslot];
            } else {
                float invz = 1.0f / s_zV[rslot];
                float4* dst = (float4*)(sm_Vn + r * DD);
#pragma unroll
                for (int i = 0; i < 4; i++) {
                    float4 v = rsrc[lane + 32 * i];
                    dst[lane + 32 * i] = make_float4(v.x * invz, v.y * invz,
                                                     v.z * invz, v.w * invz);
                }
            }
        }

        if (t + 1 < TT) __pipeline_wait_prior(0);
        __syncthreads();   // B: s_rel + s_Vn + staged buffers + prefetched rows visible

        // ---- softmax + readout: V-warps only (K-warps race ahead) ----
        if (isV) {
            float x = s_rel[lane & 7] * scale;
            float m = x;
#pragma unroll
            for (int o = 4; o > 0; o >>= 1) m = fmaxf(m, __shfl_xor_sync(0xffffffffu, m, o));
            float e = expf(x - m);
            float ssum = e;
#pragma unroll
            for (int o = 4; o > 0; o >>= 1) ssum += __shfl_xor_sync(0xffffffffu, ssum, o);
            float a = e / ssum;
            float attn[8];
#pragma unroll
            for (int q = 0; q < 8; q++) attn[q] = __shfl_sync(0xffffffffu, a, q);
            int d0 = (warp - 8) * 32 + lane;     // 0..255
            float acc0 = 0.f, acc1 = 0.f;
#pragma unroll
            for (int i = 0; i < 8; i++) {
                acc0 += attn[i] * sm_Vn[i * DD + d0];
                acc1 += attn[i] * sm_Vn[i * DD + d0 + 256];
            }
            g_RO[(size_t)bt * DD + d0]       = acc0;
            g_RO[(size_t)bt * DD + d0 + 256] = acc1;
        }
        // no barrier here: Vn/s_rel writers for t+1 are behind A(t+1)/B(t+1)
    }

    __syncthreads();
    for (int i = tid; i < MM; i += 512) { zKb[i] = s_zK[i]; zVb[i] = s_zV[i]; }
}

// ---------------- launch ----------------
extern "C" void kernel_launch(void* const* d_in, const int* in_sizes, int n_in,
                              void* d_out, int out_size)
{
    const float* h      = (const float*)d_in[0];
    const float* Kslots = (const float*)d_in[1];
    const float* Vslots = (const float*)d_in[2];
    const float* zKin   = (const float*)d_in[3];
    const float* zVin   = (const float*)d_in[4];
    const float* W_k    = (const float*)d_in[5];
    const float* W_q    = (const float*)d_in[6];
    const float* ltw    = (const float*)d_in[7];
    const float* ltr    = (const float*)d_in[8];
    const float* hh_k   = (const float*)d_in[9];
    const float* hh_vk  = (const float*)d_in[10];
    const float* hh_vv  = (const float*)d_in[11];
    const float* hh_bw  = (const float*)d_in[12];
    const float* hh_bb  = (const float*)d_in[13];
    const float* gamma  = (const float*)d_in[14];
    const float* W_out  = (const float*)d_in[15];
    const float* W_gate = (const float*)d_in[16];

    float* out    = (float*)d_out;
    float* o_outs = out;
    float* o_K    = o_outs + (size_t)BB * TT * DD;
    float* o_V    = o_K    + (size_t)BB * MM * DD;
    float* o_zK   = o_V    + (size_t)BB * MM * DD;
    float* o_zV   = o_zK   + BB * MM;
    float* o_wi   = o_zV   + BB * MM;
    float* o_ri   = o_wi   + BB * TOPK;

    cudaFuncSetAttribute(seq_kernel, cudaFuncAttributeMaxDynamicSharedMemorySize,
                         SEQ_SMEM_FLOATS * (int)sizeof(float));

    init_kernel<<<(BB * MM * DD / 4 + 255) / 256, 256>>>(Kslots, Vslots, zKin, zVin,
                                                         o_K, o_V, o_zK, o_zV);
    addr_kernel<<<BT, 64>>>(h, W_k, W_q, ltw, ltr, gamma, o_wi, o_ri);
    mega_gemm<<<dim3(28, 8), 256>>>(h, hh_k, hh_vk, hh_vv, W_gate);
    norm_kernel<<<BT * NHH, 128>>>(h, hh_bw, hh_bb);

    seq_kernel<<<BB, 512, SEQ_SMEM_FLOATS * sizeof(float)>>>(h, o_K, o_V, o_zK, o_zV);

    out_gemm<<<dim3(8, 16), 256>>>(W_out, o_outs);
}